// round 1
// baseline (speedup 1.0000x reference)
#include <cuda_runtime.h>
#include <math.h>

#define NTOK 16384
#define DMODEL 1024
#define FF 4096
#define NEXP 8
#define CAP 2560
#define NA (NTOK*2)

// ---------------- device scratch (static, allocation-free) ----------------
__device__ float g_buf[(size_t)NEXP*CAP*DMODEL];   //  84 MB dispatch buffer
__device__ float g_h  [(size_t)NEXP*CAP*FF];       // 335 MB hidden activations
__device__ float g_y  [(size_t)NEXP*CAP*DMODEL];   //  84 MB expert outputs
__device__ int   g_topi[NA];
__device__ float g_topv[NA];
__device__ int   g_apos[NA];        // slot position within expert, -1 if dropped
__device__ int   g_slot_a[NEXP*CAP]; // assignment index occupying each slot
__device__ int   g_kept[NEXP];       // kept (<=CAP) count per expert

// ---------------- router: logits -> softmax -> top2 ----------------
__global__ void __launch_bounds__(256) router_kernel(const float* __restrict__ x,
                                                     const float* __restrict__ wr,
                                                     const float* __restrict__ br) {
    __shared__ float swT[NEXP][DMODEL];   // transposed router weights, 32 KB
    int tid = threadIdx.x;
    for (int i = tid; i < DMODEL*NEXP; i += 256) {
        int d = i >> 3, e = i & 7;
        swT[e][d] = wr[i];
    }
    __syncthreads();
    int warp = tid >> 5, lane = tid & 31;
    int token = blockIdx.x * 8 + warp;
    const float* xr = x + (size_t)token * DMODEL;
    float p[NEXP];
#pragma unroll
    for (int e = 0; e < NEXP; e++) p[e] = 0.f;
    for (int j = lane; j < DMODEL; j += 32) {
        float xv = xr[j];
#pragma unroll
        for (int e = 0; e < NEXP; e++) p[e] = fmaf(xv, swT[e][j], p[e]);
    }
#pragma unroll
    for (int e = 0; e < NEXP; e++) {
#pragma unroll
        for (int off = 16; off; off >>= 1)
            p[e] += __shfl_xor_sync(0xffffffffu, p[e], off);
    }
    if (lane == 0) {
        float mx = -1e30f;
#pragma unroll
        for (int e = 0; e < NEXP; e++) { p[e] += br[e]; mx = fmaxf(mx, p[e]); }
        float s = 0.f;
#pragma unroll
        for (int e = 0; e < NEXP; e++) { p[e] = expf(p[e] - mx); s += p[e]; }
        float inv = 1.f / s;
#pragma unroll
        for (int e = 0; e < NEXP; e++) p[e] *= inv;
        // top-1 (first occurrence on ties, matching lax.top_k)
        int b0 = 0; float v0 = p[0];
#pragma unroll
        for (int e = 1; e < NEXP; e++) if (p[e] > v0) { v0 = p[e]; b0 = e; }
        int b1 = -1; float v1 = -1.f;
#pragma unroll
        for (int e = 0; e < NEXP; e++) if (e != b0 && p[e] > v1) { v1 = p[e]; b1 = e; }
        g_topi[token*2]   = b0;  g_topv[token*2]   = v0;
        g_topi[token*2+1] = b1;  g_topv[token*2+1] = v1;
    }
}

// ---------------- arrival-order capacity scan (1 block, exact order) ----------------
__global__ void __launch_bounds__(1024) scan_kernel() {
    __shared__ int scnt[1024][NEXP];    // 32 KB
    int tid = threadIdx.x;
    int cnt[NEXP];
#pragma unroll
    for (int e = 0; e < NEXP; e++) cnt[e] = 0;
    int a0 = tid * 32;
    for (int i = 0; i < 32; i++) cnt[g_topi[a0 + i]]++;
#pragma unroll
    for (int e = 0; e < NEXP; e++) scnt[tid][e] = cnt[e];
    __syncthreads();
    if (tid < NEXP) {
        int run = 0;
        for (int i = 0; i < 1024; i++) { int t = scnt[i][tid]; scnt[i][tid] = run; run += t; }
        g_kept[tid] = run < CAP ? run : CAP;
    }
    __syncthreads();
    int base[NEXP];
#pragma unroll
    for (int e = 0; e < NEXP; e++) base[e] = scnt[tid][e];
    for (int i = 0; i < 32; i++) {
        int a = a0 + i;
        int e = g_topi[a];
        int pos = base[e]++;
        if (pos < CAP) { g_apos[a] = pos; g_slot_a[e * CAP + pos] = a; }
        else           { g_apos[a] = -1; }
    }
}

// ---------------- dispatch gather: buf[e,pos,:] = x[token,:] ----------------
__global__ void __launch_bounds__(256) dispatch_kernel(const float* __restrict__ x) {
    int r = blockIdx.x;                 // [0, NEXP*CAP)
    int e = r / CAP, pos = r - e * CAP;
    float4* dst = (float4*)(g_buf + (size_t)r * DMODEL);
    if (pos < g_kept[e]) {
        int a = g_slot_a[r];
        const float4* src = (const float4*)(x + (size_t)(a >> 1) * DMODEL);
        dst[threadIdx.x] = src[threadIdx.x];
    } else {
        dst[threadIdx.x] = make_float4(0.f, 0.f, 0.f, 0.f);
    }
}

// ---------------- batched SGEMM 128x128x16, 8x8 per thread ----------------
// C[z] = A[z] (MxK row-major) @ B[z] (KxN row-major) + bias[z]; optional exact GELU.
__global__ void __launch_bounds__(256) sgemm_kernel(
    const float* __restrict__ Ab, const float* __restrict__ Bb,
    const float* __restrict__ biasb, float* __restrict__ Cb,
    int M, int N, int K, int gelu_flag,
    long sA, long sB, long sBias, long sC)
{
    const float* A = Ab + (size_t)blockIdx.z * sA;
    const float* B = Bb + (size_t)blockIdx.z * sB;
    const float* bias = biasb + (size_t)blockIdx.z * sBias;
    float* C = Cb + (size_t)blockIdx.z * sC;

    __shared__ float As[16][128];
    __shared__ float Bs[16][128];

    int tid = threadIdx.x;
    int bm = blockIdx.y * 128, bn = blockIdx.x * 128;
    int tr = (tid >> 4) * 8, tc = (tid & 15) * 8;

    float acc[8][8];
#pragma unroll
    for (int m = 0; m < 8; m++)
#pragma unroll
        for (int n = 0; n < 8; n++) acc[m][n] = 0.f;

    for (int k0 = 0; k0 < K; k0 += 16) {
        // A tile: 128 rows x 16 k, float4 along K, store transposed
#pragma unroll
        for (int l = 0; l < 2; l++) {
            int i = tid + l * 256;
            int row = i >> 2, kq = (i & 3) * 4;
            float4 v = *(const float4*)(A + (size_t)(bm + row) * K + k0 + kq);
            As[kq + 0][row] = v.x; As[kq + 1][row] = v.y;
            As[kq + 2][row] = v.z; As[kq + 3][row] = v.w;
        }
        // B tile: 16 k-rows x 128 n
#pragma unroll
        for (int l = 0; l < 2; l++) {
            int i = tid + l * 256;
            int kr = i >> 5, nq = (i & 31) * 4;
            *(float4*)(&Bs[kr][nq]) = *(const float4*)(B + (size_t)(k0 + kr) * N + bn + nq);
        }
        __syncthreads();
#pragma unroll
        for (int k = 0; k < 16; k++) {
            float a[8], b[8];
#pragma unroll
            for (int m = 0; m < 8; m++) a[m] = As[k][tr + m];
#pragma unroll
            for (int n = 0; n < 8; n++) b[n] = Bs[k][tc + n];
#pragma unroll
            for (int m = 0; m < 8; m++)
#pragma unroll
                for (int n = 0; n < 8; n++) acc[m][n] = fmaf(a[m], b[n], acc[m][n]);
        }
        __syncthreads();
    }

    // epilogue: bias (+ exact GELU), float4 stores
#pragma unroll
    for (int m = 0; m < 8; m++) {
#pragma unroll
        for (int nq = 0; nq < 2; nq++) {
            float4 v;
            float* vp = &v.x;
#pragma unroll
            for (int j = 0; j < 4; j++) {
                int n = nq * 4 + j;
                float t = acc[m][n] + bias[bn + tc + n];
                if (gelu_flag) t = 0.5f * t * (1.0f + erff(t * 0.70710678118654752f));
                vp[j] = t;
            }
            *(float4*)(C + (size_t)(bm + tr + m) * N + bn + tc + nq * 4) = v;
        }
    }
}

// ---------------- combine: weighted scatter back to tokens + normalize ----------------
__global__ void __launch_bounds__(256) combine_kernel(float* __restrict__ out) {
    int token = blockIdx.x;
    int a0 = token * 2;
    int p0 = g_apos[a0], p1 = g_apos[a0 + 1];
    float w0 = (p0 >= 0) ? g_topv[a0]     : 0.f;
    float w1 = (p1 >= 0) ? g_topv[a0 + 1] : 0.f;
    float ws = w0 + w1;
    int t4 = threadIdx.x;
    float4 acc = make_float4(0.f, 0.f, 0.f, 0.f);
    if (p0 >= 0) {
        const float4* r = (const float4*)(g_y + ((size_t)g_topi[a0] * CAP + p0) * DMODEL);
        float4 v = r[t4];
        acc.x = fmaf(w0, v.x, acc.x); acc.y = fmaf(w0, v.y, acc.y);
        acc.z = fmaf(w0, v.z, acc.z); acc.w = fmaf(w0, v.w, acc.w);
    }
    if (p1 >= 0) {
        const float4* r = (const float4*)(g_y + ((size_t)g_topi[a0 + 1] * CAP + p1) * DMODEL);
        float4 v = r[t4];
        acc.x = fmaf(w1, v.x, acc.x); acc.y = fmaf(w1, v.y, acc.y);
        acc.z = fmaf(w1, v.z, acc.z); acc.w = fmaf(w1, v.w, acc.w);
    }
    if (ws > 0.f) {
        float inv = 1.f / fmaxf(ws, 1e-6f);
        acc.x *= inv; acc.y *= inv; acc.z *= inv; acc.w *= inv;
    }
    ((float4*)(out + (size_t)token * DMODEL))[t4] = acc;
}

// ---------------- launch ----------------
extern "C" void kernel_launch(void* const* d_in, const int* in_sizes, int n_in,
                              void* d_out, int out_size) {
    const float* x  = (const float*)d_in[0];
    const float* wr = (const float*)d_in[1];
    const float* br = (const float*)d_in[2];
    const float* w1 = (const float*)d_in[3];
    const float* b1 = (const float*)d_in[4];
    const float* w2 = (const float*)d_in[5];
    const float* b2 = (const float*)d_in[6];
    float* y = (float*)d_out;

    float *buf, *h, *yy;
    cudaGetSymbolAddress((void**)&buf, g_buf);
    cudaGetSymbolAddress((void**)&h,   g_h);
    cudaGetSymbolAddress((void**)&yy,  g_y);

    router_kernel<<<NTOK / 8, 256>>>(x, wr, br);
    scan_kernel<<<1, 1024>>>();
    dispatch_kernel<<<NEXP * CAP, 256>>>(x);

    dim3 g1(FF / 128, CAP / 128, NEXP);       // 32 x 20 x 8
    sgemm_kernel<<<g1, 256>>>(buf, w1, b1, h, CAP, FF, DMODEL, 1,
                              (long)CAP * DMODEL, (long)DMODEL * FF, FF, (long)CAP * FF);

    dim3 g2(DMODEL / 128, CAP / 128, NEXP);   // 8 x 20 x 8
    sgemm_kernel<<<g2, 256>>>(h, w2, b2, yy, CAP, DMODEL, FF, 0,
                              (long)CAP * FF, (long)FF * DMODEL, DMODEL, (long)CAP * DMODEL);

    combine_kernel<<<NTOK, 256>>>(y);
}

// round 3
// speedup vs baseline: 2.8570x; 2.8570x over previous
#include <cuda_runtime.h>
#include <math.h>
#include <stdint.h>

#define NTOK 16384
#define DMODEL 1024
#define FF 4096
#define NEXP 8
#define CAP 2560
#define NA (NTOK*2)

// ---------------- device scratch (static, allocation-free) ----------------
__device__ float g_buf[(size_t)NEXP*CAP*DMODEL];   //  84 MB dispatch buffer
__device__ float g_h  [(size_t)NEXP*CAP*FF];       // 335 MB hidden activations
__device__ float g_y  [(size_t)NEXP*CAP*DMODEL];   //  84 MB expert outputs
__device__ int   g_topi[NA];
__device__ float g_topv[NA];
__device__ int   g_apos[NA];
__device__ int   g_slot_a[NEXP*CAP];
__device__ int   g_kept[NEXP];

__device__ __forceinline__ uint32_t f2tf32(float f) {
    uint32_t u; asm("cvt.rna.tf32.f32 %0, %1;" : "=r"(u) : "f"(f)); return u;
}
__device__ __forceinline__ void mma_tf32(float* d, const uint32_t* a, const uint32_t* b) {
    asm volatile("mma.sync.aligned.m16n8k8.row.col.f32.tf32.tf32.f32 "
        "{%0,%1,%2,%3}, {%4,%5,%6,%7}, {%8,%9}, {%0,%1,%2,%3};"
        : "+f"(d[0]), "+f"(d[1]), "+f"(d[2]), "+f"(d[3])
        : "r"(a[0]), "r"(a[1]), "r"(a[2]), "r"(a[3]), "r"(b[0]), "r"(b[1]));
}

// ---------------- tf32 tensor-core grouped GEMM ----------------
// C[z] = A[z](MxK row-major) @ B[z](KxN row-major) + bias[z], optional exact GELU.
// CTA tile 128x128, k-chunk 16, 8 warps (2m x 4n), warp tile 64x32.
#define ASTRIDE 20     // floats per A smem row (16 data + 4 pad) -> conflict-free frag reads
#define BSTRIDE 136    // floats per B smem row (128 data + 8 pad)

__global__ void __launch_bounds__(256, 2) moe_mma_kernel(
    const float* __restrict__ Ab, const float* __restrict__ Bb,
    const float* __restrict__ biasb, float* __restrict__ Cb,
    int M, int N, int K, int gelu_flag,
    long sA, long sB, long sBias, long sC)
{
    __shared__ float As[2][128 * ASTRIDE];   // 2 x 10240B
    __shared__ float Bs[2][16 * BSTRIDE];    // 2 x 8704B

    const float* A = Ab + (size_t)blockIdx.z * sA;
    const float* B = Bb + (size_t)blockIdx.z * sB;
    const float* bias = biasb + (size_t)blockIdx.z * sBias;
    float* C = Cb + (size_t)blockIdx.z * sC;

    const int tid = threadIdx.x;
    const int wid = tid >> 5, lane = tid & 31;
    const int wm = wid >> 2;          // 0..1  -> m offset wm*64
    const int wn = wid & 3;           // 0..3  -> n offset wn*32
    const int g = lane >> 2;          // group id 0..7
    const int t = lane & 3;           // thread-in-group 0..3
    const int bm = blockIdx.x * 128;
    const int bn = blockIdx.y * 128;

    // per-thread load coords
    const int a_row = tid >> 2;                 // 0..63  (x2 halves)
    const int a_k4  = (tid & 3) * 4;            // k offset 0,4,8,12
    const int b_kr  = tid >> 5;                 // 0..7   (x2 halves)
    const int b_n4  = (tid & 31) * 4;           // n offset

    float acc[4][4][4];
#pragma unroll
    for (int mt = 0; mt < 4; mt++)
#pragma unroll
        for (int nt = 0; nt < 4; nt++)
#pragma unroll
            for (int q = 0; q < 4; q++) acc[mt][nt][q] = 0.f;

    const int nch = K >> 4;
    float4 pa[2], pb[2];

    // prefetch chunk 0
    {
        const float* Ag = A + (size_t)bm * K;
        const float* Bg = B + bn;
#pragma unroll
        for (int l = 0; l < 2; l++) {
            pa[l] = *(const float4*)(Ag + (size_t)(a_row + l * 64) * K + a_k4);
            pb[l] = *(const float4*)(Bg + (size_t)(b_kr + l * 8) * N + b_n4);
        }
    }
    // store chunk 0
#pragma unroll
    for (int l = 0; l < 2; l++) {
        uint32_t ua[4] = { f2tf32(pa[l].x), f2tf32(pa[l].y), f2tf32(pa[l].z), f2tf32(pa[l].w) };
        *(uint4*)&As[0][(a_row + l * 64) * ASTRIDE + a_k4] = make_uint4(ua[0], ua[1], ua[2], ua[3]);
        uint32_t ub[4] = { f2tf32(pb[l].x), f2tf32(pb[l].y), f2tf32(pb[l].z), f2tf32(pb[l].w) };
        *(uint4*)&Bs[0][(b_kr + l * 8) * BSTRIDE + b_n4] = make_uint4(ub[0], ub[1], ub[2], ub[3]);
    }
    __syncthreads();

    for (int i = 0; i < nch; i++) {
        const int buf = i & 1;
        // prefetch next chunk (global -> regs)
        if (i + 1 < nch) {
            const int k0 = (i + 1) << 4;
            const float* Ag = A + (size_t)bm * K + k0;
            const float* Bg = B + (size_t)k0 * N + bn;
#pragma unroll
            for (int l = 0; l < 2; l++) {
                pa[l] = *(const float4*)(Ag + (size_t)(a_row + l * 64) * K + a_k4);
                pb[l] = *(const float4*)(Bg + (size_t)(b_kr + l * 8) * N + b_n4);
            }
        }
        // compute current chunk
        const float* as = As[buf];
        const float* bs = Bs[buf];
#pragma unroll
        for (int kk = 0; kk < 2; kk++) {
            uint32_t af[4][4], bf[4][2];
#pragma unroll
            for (int mt = 0; mt < 4; mt++) {
                const int r0 = (wm * 64 + mt * 16 + g) * ASTRIDE + kk * 8 + t;
                af[mt][0] = __float_as_uint(as[r0]);
                af[mt][1] = __float_as_uint(as[r0 + 8 * ASTRIDE]);
                af[mt][2] = __float_as_uint(as[r0 + 4]);
                af[mt][3] = __float_as_uint(as[r0 + 8 * ASTRIDE + 4]);
            }
#pragma unroll
            for (int nt = 0; nt < 4; nt++) {
                const int c0 = (kk * 8 + t) * BSTRIDE + wn * 32 + nt * 8 + g;
                bf[nt][0] = __float_as_uint(bs[c0]);
                bf[nt][1] = __float_as_uint(bs[c0 + 4 * BSTRIDE]);
            }
#pragma unroll
            for (int mt = 0; mt < 4; mt++)
#pragma unroll
                for (int nt = 0; nt < 4; nt++)
                    mma_tf32(acc[mt][nt], af[mt], bf[nt]);
        }
        // stage next chunk to smem
        if (i + 1 < nch) {
            const int nb = buf ^ 1;
#pragma unroll
            for (int l = 0; l < 2; l++) {
                uint32_t ua[4] = { f2tf32(pa[l].x), f2tf32(pa[l].y), f2tf32(pa[l].z), f2tf32(pa[l].w) };
                *(uint4*)&As[nb][(a_row + l * 64) * ASTRIDE + a_k4] = make_uint4(ua[0], ua[1], ua[2], ua[3]);
                uint32_t ub[4] = { f2tf32(pb[l].x), f2tf32(pb[l].y), f2tf32(pb[l].z), f2tf32(pb[l].w) };
                *(uint4*)&Bs[nb][(b_kr + l * 8) * BSTRIDE + b_n4] = make_uint4(ub[0], ub[1], ub[2], ub[3]);
            }
            __syncthreads();
        }
    }

    // ---- epilogue: bias + optional exact GELU, float2 stores ----
#pragma unroll
    for (int mt = 0; mt < 4; mt++) {
#pragma unroll
        for (int nt = 0; nt < 4; nt++) {
            const int row = bm + wm * 64 + mt * 16 + g;
            const int col = bn + wn * 32 + nt * 8 + 2 * t;
            const float bz0 = bias[col], bz1 = bias[col + 1];
            float v[4] = { acc[mt][nt][0] + bz0, acc[mt][nt][1] + bz1,
                           acc[mt][nt][2] + bz0, acc[mt][nt][3] + bz1 };
            if (gelu_flag) {
#pragma unroll
                for (int q = 0; q < 4; q++)
                    v[q] = 0.5f * v[q] * (1.0f + erff(v[q] * 0.70710678118654752f));
            }
            *(float2*)(C + (size_t)row * N + col)       = make_float2(v[0], v[1]);
            *(float2*)(C + (size_t)(row + 8) * N + col) = make_float2(v[2], v[3]);
        }
    }
}

// ---------------- router: logits -> softmax -> top2 ----------------
__global__ void __launch_bounds__(256) router_kernel(const float* __restrict__ x,
                                                     const float* __restrict__ wr,
                                                     const float* __restrict__ br) {
    __shared__ float swT[NEXP][DMODEL];
    int tid = threadIdx.x;
    for (int i = tid; i < DMODEL * NEXP; i += 256) {
        int d = i >> 3, e = i & 7;
        swT[e][d] = wr[i];
    }
    __syncthreads();
    int warp = tid >> 5, lane = tid & 31;
    int token = blockIdx.x * 8 + warp;
    const float* xr = x + (size_t)token * DMODEL;
    float p[NEXP];
#pragma unroll
    for (int e = 0; e < NEXP; e++) p[e] = 0.f;
    for (int j = lane; j < DMODEL; j += 32) {
        float xv = xr[j];
#pragma unroll
        for (int e = 0; e < NEXP; e++) p[e] = fmaf(xv, swT[e][j], p[e]);
    }
#pragma unroll
    for (int e = 0; e < NEXP; e++) {
#pragma unroll
        for (int off = 16; off; off >>= 1)
            p[e] += __shfl_xor_sync(0xffffffffu, p[e], off);
    }
    if (lane == 0) {
        float mx = -1e30f;
#pragma unroll
        for (int e = 0; e < NEXP; e++) { p[e] += br[e]; mx = fmaxf(mx, p[e]); }
        float s = 0.f;
#pragma unroll
        for (int e = 0; e < NEXP; e++) { p[e] = expf(p[e] - mx); s += p[e]; }
        float inv = 1.f / s;
#pragma unroll
        for (int e = 0; e < NEXP; e++) p[e] *= inv;
        int b0 = 0; float v0 = p[0];
#pragma unroll
        for (int e = 1; e < NEXP; e++) if (p[e] > v0) { v0 = p[e]; b0 = e; }
        int b1 = -1; float v1 = -1.f;
#pragma unroll
        for (int e = 0; e < NEXP; e++) if (e != b0 && p[e] > v1) { v1 = p[e]; b1 = e; }
        g_topi[token*2]   = b0;  g_topv[token*2]   = v0;
        g_topi[token*2+1] = b1;  g_topv[token*2+1] = v1;
    }
}

// ---------------- arrival-order capacity scan ----------------
__global__ void __launch_bounds__(1024) scan_kernel() {
    __shared__ int scnt[1024][NEXP];
    int tid = threadIdx.x;
    int cnt[NEXP];
#pragma unroll
    for (int e = 0; e < NEXP; e++) cnt[e] = 0;
    int a0 = tid * 32;
    for (int i = 0; i < 32; i++) cnt[g_topi[a0 + i]]++;
#pragma unroll
    for (int e = 0; e < NEXP; e++) scnt[tid][e] = cnt[e];
    __syncthreads();
    if (tid < NEXP) {
        int run = 0;
        for (int i = 0; i < 1024; i++) { int tv = scnt[i][tid]; scnt[i][tid] = run; run += tv; }
        g_kept[tid] = run < CAP ? run : CAP;
    }
    __syncthreads();
    int base[NEXP];
#pragma unroll
    for (int e = 0; e < NEXP; e++) base[e] = scnt[tid][e];
    for (int i = 0; i < 32; i++) {
        int a = a0 + i;
        int e = g_topi[a];
        int pos = base[e]++;
        if (pos < CAP) { g_apos[a] = pos; g_slot_a[e * CAP + pos] = a; }
        else           { g_apos[a] = -1; }
    }
}

// ---------------- dispatch gather ----------------
__global__ void __launch_bounds__(256) dispatch_kernel(const float* __restrict__ x) {
    int r = blockIdx.x;
    int e = r / CAP, pos = r - e * CAP;
    float4* dst = (float4*)(g_buf + (size_t)r * DMODEL);
    if (pos < g_kept[e]) {
        int a = g_slot_a[r];
        const float4* src = (const float4*)(x + (size_t)(a >> 1) * DMODEL);
        dst[threadIdx.x] = src[threadIdx.x];
    } else {
        dst[threadIdx.x] = make_float4(0.f, 0.f, 0.f, 0.f);
    }
}

// ---------------- combine ----------------
__global__ void __launch_bounds__(256) combine_kernel(float* __restrict__ out) {
    int token = blockIdx.x;
    int a0 = token * 2;
    int p0 = g_apos[a0], p1 = g_apos[a0 + 1];
    float w0 = (p0 >= 0) ? g_topv[a0]     : 0.f;
    float w1 = (p1 >= 0) ? g_topv[a0 + 1] : 0.f;
    float ws = w0 + w1;
    int t4 = threadIdx.x;
    float4 acc = make_float4(0.f, 0.f, 0.f, 0.f);
    if (p0 >= 0) {
        const float4* r = (const float4*)(g_y + ((size_t)g_topi[a0] * CAP + p0) * DMODEL);
        float4 v = r[t4];
        acc.x = fmaf(w0, v.x, acc.x); acc.y = fmaf(w0, v.y, acc.y);
        acc.z = fmaf(w0, v.z, acc.z); acc.w = fmaf(w0, v.w, acc.w);
    }
    if (p1 >= 0) {
        const float4* r = (const float4*)(g_y + ((size_t)g_topi[a0 + 1] * CAP + p1) * DMODEL);
        float4 v = r[t4];
        acc.x = fmaf(w1, v.x, acc.x); acc.y = fmaf(w1, v.y, acc.y);
        acc.z = fmaf(w1, v.z, acc.z); acc.w = fmaf(w1, v.w, acc.w);
    }
    if (ws > 0.f) {
        float inv = 1.f / fmaxf(ws, 1e-6f);
        acc.x *= inv; acc.y *= inv; acc.z *= inv; acc.w *= inv;
    }
    ((float4*)(out + (size_t)token * DMODEL))[t4] = acc;
}

// ---------------- launch ----------------
extern "C" void kernel_launch(void* const* d_in, const int* in_sizes, int n_in,
                              void* d_out, int out_size) {
    const float* x  = (const float*)d_in[0];
    const float* wr = (const float*)d_in[1];
    const float* br = (const float*)d_in[2];
    const float* w1 = (const float*)d_in[3];
    const float* b1 = (const float*)d_in[4];
    const float* w2 = (const float*)d_in[5];
    const float* b2 = (const float*)d_in[6];
    float* y = (float*)d_out;

    float *buf, *h, *yy;
    cudaGetSymbolAddress((void**)&buf, g_buf);
    cudaGetSymbolAddress((void**)&h,   g_h);
    cudaGetSymbolAddress((void**)&yy,  g_y);

    router_kernel<<<NTOK / 8, 256>>>(x, wr, br);
    scan_kernel<<<1, 1024>>>();
    dispatch_kernel<<<NEXP * CAP, 256>>>(x);

    // GEMM1: h = GELU(buf @ w1 + b1)   [per expert: 2560x1024 @ 1024x4096]
    dim3 g1(CAP / 128, FF / 128, NEXP);       // 20 x 32 x 8
    moe_mma_kernel<<<g1, 256>>>(buf, w1, b1, h, CAP, FF, DMODEL, 1,
                              (long)CAP * DMODEL, (long)DMODEL * FF, FF, (long)CAP * FF);

    // GEMM2: y_e = h @ w2 + b2          [per expert: 2560x4096 @ 4096x1024]
    dim3 g2(CAP / 128, DMODEL / 128, NEXP);   // 20 x 8 x 8
    moe_mma_kernel<<<g2, 256>>>(h, w2, b2, yy, CAP, DMODEL, FF, 0,
                              (long)CAP * FF, (long)FF * DMODEL, DMODEL, (long)CAP * DMODEL);

    combine_kernel<<<NTOK, 256>>>(y);
}